// round 6
// baseline (speedup 1.0000x reference)
#include <cuda_runtime.h>

// CapsuleLayer dynamic routing, algebraically collapsed:
//   b[n,m] = x[n,:] @ Pacc[:,m]   (Pacc accumulates log2e * W@v across iterations)
//   s[m,:] = (1/Z) (e^T x) W[:,m,:],  v = squash(s),  Pacc[:,m] += log2e*W[:,m,:] v
// u_hat (268MB) never materialized. Softmax stabilized by Cauchy-Schwarz bound
// |l| <= max_n||x_n|| * ||Pacc_col||, in log2 domain so exp = single EX2.
// R6: x tile RESIDENT IN REGISTERS (4 rows/thread); capsules iterated serially;
//     no LDS in the inner loop. Reduction partials aliased over the dead x
//     staging buffer.

#define NROW    2048
#define DIN     16
#define XSTRIDE 20
#define THREADS 512
#define LOG2E   1.4426950408889634f

typedef unsigned long long ull;

struct Red {
  float party[16][16][2][16];   // [cap][warp][lanegrp][d]   32KB
  float partZ[16][16][2];       // [cap][warp][lanegrp]       2KB
  float yfull[16][16];          // [cap][d]
  float Zfull[16];
};

struct Smem {
  union {
    float xs[NROW * XSTRIDE];   // staging for coalesced load (dead after x->regs)
    Red   r;
  } u;
  float Wdc[16 * 16 * 16];      // [ml][d][c]
  float Wcd[16 * 16 * 16];      // [ml][c][d]
  float Pacc[16][16];           // [ml][d]  (scaled by log2e)
  float wpart[16][16];          // per-warp partial column sums of x
  float wmax[16];               // per-warp max row-norm^2
  float sumx[16];               // sum over n of x[n,d]
  float vbuf[16][16];           // [ml][c]
  float bnd[16];                // softmax shift bound per ml (log2 domain)
  float mxnorm;
  float pad[3];
};

__device__ __forceinline__ ull mul2(ull a, ull b) {
  ull d; asm("mul.rn.f32x2 %0, %1, %2;" : "=l"(d) : "l"(a), "l"(b)); return d;
}
__device__ __forceinline__ ull add2(ull a, ull b) {
  ull d; asm("add.rn.f32x2 %0, %1, %2;" : "=l"(d) : "l"(a), "l"(b)); return d;
}
__device__ __forceinline__ ull fma2(ull a, ull b, ull c) {
  ull d; asm("fma.rn.f32x2 %0, %1, %2, %3;" : "=l"(d) : "l"(a), "l"(b), "l"(c)); return d;
}
__device__ __forceinline__ ull pack2(float x) {
  ull d; asm("mov.b64 %0, {%1, %1};" : "=l"(d) : "f"(x)); return d;
}
__device__ __forceinline__ ull packlh(float lo, float hi) {
  ull d; asm("mov.b64 %0, {%1, %2};" : "=l"(d) : "f"(lo), "f"(hi)); return d;
}
__device__ __forceinline__ float hadd2(ull a) {
  float lo, hi; asm("mov.b64 {%0, %1}, %2;" : "=f"(lo), "=f"(hi) : "l"(a)); return lo + hi;
}
__device__ __forceinline__ float ex2f(float x) {
  float r; asm("ex2.approx.f32 %0, %1;" : "=f"(r) : "f"(x)); return r;
}

__global__ void __launch_bounds__(THREADS, 1)
caps_routing_kernel(const float* __restrict__ X, const float* __restrict__ Wg,
                    float* __restrict__ Y) {
  extern __shared__ char smraw[];
  Smem* sm = reinterpret_cast<Smem*>(smraw);
  const int tid  = threadIdx.x;
  const int lane = tid & 31;
  const int w    = tid >> 5;
  const int b    = blockIdx.x >> 1;
  const int m0   = (blockIdx.x & 1) * 16;

  if (tid < 16) sm->bnd[tid] = 0.f;
  if (tid < 256) ((float*)sm->Pacc)[tid] = 0.f;

  // ---- Stage x tile (128KB) into padded smem (coalesced); fold in sums/norms ----
  const float4* Xb = reinterpret_cast<const float4*>(X + (size_t)b * NROW * DIN);
  const int q = tid & 3;
  float4 s4 = make_float4(0.f, 0.f, 0.f, 0.f);
  float mloc = 0.f;
#pragma unroll
  for (int i = 0; i < 16; ++i) {
    int idx = tid + THREADS * i;
    int n = idx >> 2;
    float4 v = Xb[idx];
    *reinterpret_cast<float4*>(&sm->u.xs[n * XSTRIDE + q * 4]) = v;
    s4.x += v.x; s4.y += v.y; s4.z += v.z; s4.w += v.w;
    float qd = v.x * v.x + v.y * v.y + v.z * v.z + v.w * v.w;
    qd += __shfl_xor_sync(0xffffffffu, qd, 1);
    qd += __shfl_xor_sync(0xffffffffu, qd, 2);
    mloc = fmaxf(mloc, qd);
  }
#pragma unroll
  for (int off = 4; off < 32; off <<= 1) {
    s4.x += __shfl_xor_sync(0xffffffffu, s4.x, off);
    s4.y += __shfl_xor_sync(0xffffffffu, s4.y, off);
    s4.z += __shfl_xor_sync(0xffffffffu, s4.z, off);
    s4.w += __shfl_xor_sync(0xffffffffu, s4.w, off);
    mloc = fmaxf(mloc, __shfl_xor_sync(0xffffffffu, mloc, off));
  }
  if (lane < 4) *reinterpret_cast<float4*>(&sm->wpart[w][lane * 4]) = s4;
  if (lane == 0) sm->wmax[w] = mloc;

  // ---- Load W slices in two layouts ----
#pragma unroll
  for (int i = 0; i < 8; ++i) {
    int idx2 = tid + THREADS * i;         // [ml][d][c]
    int ml = idx2 >> 8, d = (idx2 >> 4) & 15, c = idx2 & 15;
    float val = Wg[d * 512 + (m0 + ml) * 16 + c];
    sm->Wdc[idx2] = val;
    sm->Wcd[ml * 256 + c * 16 + d] = val;
  }
  __syncthreads();

  // ---- Pull 4 rows (rows tid + 512k) from smem into registers ----
  ull xr[4][8];
#pragma unroll
  for (int r = 0; r < 4; ++r) {
    const ulonglong2* xp =
        reinterpret_cast<const ulonglong2*>(&sm->u.xs[(tid + 512 * r) * XSTRIDE]);
    ulonglong2 q0 = xp[0], q1 = xp[1], q2 = xp[2], q3 = xp[3];
    xr[r][0] = q0.x; xr[r][1] = q0.y; xr[r][2] = q1.x; xr[r][3] = q1.y;
    xr[r][4] = q2.x; xr[r][5] = q2.y; xr[r][6] = q3.x; xr[r][7] = q3.y;
  }

  if (tid < 16) {
    float s = 0.f;
#pragma unroll
    for (int ww = 0; ww < 16; ++ww) s += sm->wpart[ww][tid];
    sm->sumx[tid] = s;
  }
  if (tid == 16) {
    float mx = 0.f;
#pragma unroll
    for (int ww = 0; ww < 16; ++ww) mx = fmaxf(mx, sm->wmax[ww]);
    sm->mxnorm = sqrtf(mx);
  }
  __syncthreads();   // sumx visible; all xs reads complete (xs dead -> Red alias ok)

#pragma unroll 1
  for (int it = 0; it < 3; ++it) {
    if (it > 0) {
      // ---- per-capsule pass, x fully in registers ----
#pragma unroll 1
      for (int cap = 0; cap < 16; ++cap) {
        ull p[8];
        const ulonglong2* pp = reinterpret_cast<const ulonglong2*>(&sm->Pacc[cap][0]);
        ulonglong2 p0 = pp[0], p1 = pp[1], p2 = pp[2], p3 = pp[3];
        p[0] = p0.x; p[1] = p0.y; p[2] = p1.x; p[3] = p1.y;
        p[4] = p2.x; p[5] = p2.y; p[6] = p3.x; p[7] = p3.y;
        ull ib = packlh(-sm->bnd[cap], 0.f);

        float e[4];
#pragma unroll
        for (int r = 0; r < 4; ++r) {
          ull a0 = fma2(xr[r][0], p[0], ib);
          ull a1 = mul2(xr[r][1], p[1]);
#pragma unroll
          for (int j = 1; j < 4; ++j) {
            a0 = fma2(xr[r][2 * j],     p[2 * j],     a0);
            a1 = fma2(xr[r][2 * j + 1], p[2 * j + 1], a1);
          }
          e[r] = ex2f(hadd2(add2(a0, a1)));
        }
        float Zc = (e[0] + e[1]) + (e[2] + e[3]);
        ull e0 = pack2(e[0]), e1 = pack2(e[1]), e2 = pack2(e[2]), e3 = pack2(e[3]);
        ull y[8];
#pragma unroll
        for (int j = 0; j < 8; ++j) {
          ull t = fma2(e1, xr[1][j], mul2(e0, xr[0][j]));
          t = fma2(e2, xr[2][j], t);
          y[j] = fma2(e3, xr[3][j], t);
        }
        // 4-level shfl reduction -> 2 partials (lanes 0,1)
#pragma unroll
        for (int off = 16; off >= 2; off >>= 1) {
          Zc += __shfl_xor_sync(0xffffffffu, Zc, off);
#pragma unroll
          for (int j = 0; j < 8; ++j)
            y[j] = add2(y[j], __shfl_xor_sync(0xffffffffu, y[j], off));
        }
        if (lane < 2) {
          sm->u.r.partZ[cap][w][lane] = Zc;
#pragma unroll
          for (int j = 0; j < 8; ++j)
            *reinterpret_cast<ull*>(&sm->u.r.party[cap][w][lane][2 * j]) = y[j];
        }
      }
      __syncthreads();

      // ---- stage 1: fold 32 partials per (cap,d) and per cap ----
      if (tid < 256) {
        const int cap = tid >> 4, d = tid & 15;
        float acc = 0.f;
#pragma unroll
        for (int ww = 0; ww < 16; ++ww)
          acc += sm->u.r.party[cap][ww][0][d] + sm->u.r.party[cap][ww][1][d];
        sm->u.r.yfull[cap][d] = acc;
      } else if (tid < 272) {
        const int cap = tid - 256;
        float acc = 0.f;
#pragma unroll
        for (int ww = 0; ww < 16; ++ww)
          acc += sm->u.r.partZ[cap][ww][0] + sm->u.r.partZ[cap][ww][1];
        sm->u.r.Zfull[cap] = acc;
      }
      __syncthreads();
    }

    // ---- per-capsule epilogue: s = yW/Z, squash, Pacc += log2e * W v, bound ----
    if (w < 8) {
      const int ml  = w * 2 + (lane >> 4);
      const int idx = lane & 15;
      float Z = (it == 0) ? 2048.f : sm->u.r.Zfull[ml];
      float s = 0.f;
#pragma unroll
      for (int d = 0; d < 16; ++d) {
        float yv = (it == 0) ? sm->sumx[d] : sm->u.r.yfull[ml][d];
        s += yv * sm->Wdc[(ml * 16 + d) * 16 + idx];
      }
      s *= (1.f / Z);
      float nsq = s * s;
#pragma unroll
      for (int off = 1; off < 16; off <<= 1) nsq += __shfl_xor_sync(0xffffffffu, nsq, off);
      float norm = sqrtf(nsq);
      float fac  = nsq / ((1.f + nsq) * (norm + 1e-7f));
      float v    = s * fac;
      if (it == 2) {
        Y[(size_t)b * 512 + (m0 + ml) * 16 + idx] = v;
      } else {
        sm->vbuf[ml][idx] = v;
        __syncwarp();
        float pd = 0.f;
#pragma unroll
        for (int c = 0; c < 16; ++c)
          pd += sm->Wcd[(ml * 16 + c) * 16 + idx] * sm->vbuf[ml][c];
        float pn = sm->Pacc[ml][idx] + LOG2E * pd;
        sm->Pacc[ml][idx] = pn;
        float cn = pn * pn;
#pragma unroll
        for (int off = 1; off < 16; off <<= 1) cn += __shfl_xor_sync(0xffffffffu, cn, off);
        if (idx == 0) sm->bnd[ml] = sqrtf(cn) * sm->mxnorm;
      }
    }
    __syncthreads();
  }
}

extern "C" void kernel_launch(void* const* d_in, const int* in_sizes, int n_in,
                              void* d_out, int out_size) {
  (void)in_sizes; (void)n_in; (void)out_size;
  const float* X  = (const float*)d_in[0];   // inputs (64, 2048, 16)
  const float* Wg = (const float*)d_in[1];   // W (16, 32, 16)
  float* Y = (float*)d_out;                  // v (64, 32, 16)
  cudaFuncSetAttribute(caps_routing_kernel,
                       cudaFuncAttributeMaxDynamicSharedMemorySize, (int)sizeof(Smem));
  caps_routing_kernel<<<128, THREADS, sizeof(Smem)>>>(X, Wg, Y);
}

// round 7
// speedup vs baseline: 1.2098x; 1.2098x over previous
#include <cuda_runtime.h>

// CapsuleLayer dynamic routing, algebraically collapsed:
//   b[n,m] = x[n,:] @ Pacc[:,m]   (Pacc accumulates log2e * W@v across iterations)
//   s[m,:] = (1/Z) (e^T x) W[:,m,:],  v = squash(s),  Pacc[:,m] += log2e*W[:,m,:] v
// u_hat (268MB) never materialized. Softmax stabilized by Cauchy-Schwarz bound
// |l| <= max_n||x_n|| * ||Pacc_col||, in log2 domain so exp = single EX2.
// R7: C=4 capsules/warp at 384 threads (12 warps = 4 cap-quads x 3 row-chunks,
//     170-reg budget, no spill). Halves LDS crossbar traffic vs C=2 so the FMA
//     pipe is the sole floor; 4 independent logit/EX2 chains per step.

#define NROW    2048
#define DIN     16
#define XSTRIDE 20
#define THREADS 384
#define LOG2E   1.4426950408889634f

typedef unsigned long long ull;

struct Red {
  float party[16][3][2][16];    // [cap][chunk][lanegrp][d]
  float partZ[16][3][2];        // [cap][chunk][lanegrp]
  float yfull[16][16];          // [cap][d]
  float Zfull[16];
};

struct Smem {
  union {
    float xs[NROW * XSTRIDE];   // padded x rows (conflict-free stride 80B)
    // NOTE: xs stays live through the whole kernel (main loop reads it);
    // Red must NOT alias xs. Kept separate below.
  } u;
  Red   r;
  float Wdc[16 * 16 * 16];      // [ml][d][c]
  float Wcd[16 * 16 * 16];      // [ml][c][d]
  float Pacc[16][16];           // [ml][d]  (scaled by log2e)
  float wpart[12][16];          // per-warp partial column sums of x
  float wmax[12];               // per-warp max row-norm^2
  float sumx[16];               // sum over n of x[n,d]
  float vbuf[16][16];           // [ml][c]
  float bnd[16];                // softmax shift bound per ml (log2 domain)
  float mxnorm;
  float pad[3];
};

__device__ __forceinline__ ull mul2(ull a, ull b) {
  ull d; asm("mul.rn.f32x2 %0, %1, %2;" : "=l"(d) : "l"(a), "l"(b)); return d;
}
__device__ __forceinline__ ull add2(ull a, ull b) {
  ull d; asm("add.rn.f32x2 %0, %1, %2;" : "=l"(d) : "l"(a), "l"(b)); return d;
}
__device__ __forceinline__ ull fma2(ull a, ull b, ull c) {
  ull d; asm("fma.rn.f32x2 %0, %1, %2, %3;" : "=l"(d) : "l"(a), "l"(b), "l"(c)); return d;
}
__device__ __forceinline__ ull pack2(float x) {
  ull d; asm("mov.b64 %0, {%1, %1};" : "=l"(d) : "f"(x)); return d;
}
__device__ __forceinline__ ull packlh(float lo, float hi) {
  ull d; asm("mov.b64 %0, {%1, %2};" : "=l"(d) : "f"(lo), "f"(hi)); return d;
}
__device__ __forceinline__ float hadd2(ull a) {
  float lo, hi; asm("mov.b64 {%0, %1}, %2;" : "=f"(lo), "=f"(hi) : "l"(a)); return lo + hi;
}
__device__ __forceinline__ float ex2f(float x) {
  float r; asm("ex2.approx.f32 %0, %1;" : "=f"(r) : "f"(x)); return r;
}

__device__ __forceinline__ void loadx(ull (&dst)[8], const float* base) {
  const ulonglong2* xp = reinterpret_cast<const ulonglong2*>(base);
  ulonglong2 q0 = xp[0], q1 = xp[1], q2 = xp[2], q3 = xp[3];
  dst[0] = q0.x; dst[1] = q0.y; dst[2] = q1.x; dst[3] = q1.y;
  dst[4] = q2.x; dst[5] = q2.y; dst[6] = q3.x; dst[7] = q3.y;
}

__global__ void __launch_bounds__(THREADS, 1)
caps_routing_kernel(const float* __restrict__ X, const float* __restrict__ Wg,
                    float* __restrict__ Y) {
  extern __shared__ char smraw[];
  Smem* sm = reinterpret_cast<Smem*>(smraw);
  const int tid  = threadIdx.x;
  const int lane = tid & 31;
  const int w    = tid >> 5;
  const int b    = blockIdx.x >> 1;
  const int m0   = (blockIdx.x & 1) * 16;

  if (tid < 256) ((float*)sm->Pacc)[tid] = 0.f;
  if (tid < 16)  sm->bnd[tid] = 0.f;

  // ---- Load x tile (128KB) into padded smem; fold in column sums + max row norm ----
  const float4* Xb = reinterpret_cast<const float4*>(X + (size_t)b * NROW * DIN);
  const int q = tid & 3;   // constant quarter per thread (384 % 4 == 0)
  float4 s4 = make_float4(0.f, 0.f, 0.f, 0.f);
  float mloc = 0.f;
#pragma unroll 1
  for (int idx = tid; idx < NROW * 4; idx += THREADS) {   // warps stay uniform
    int n = idx >> 2;
    float4 v = Xb[idx];
    *reinterpret_cast<float4*>(&sm->u.xs[n * XSTRIDE + q * 4]) = v;
    s4.x += v.x; s4.y += v.y; s4.z += v.z; s4.w += v.w;
    float qd = v.x * v.x + v.y * v.y + v.z * v.z + v.w * v.w;
    qd += __shfl_xor_sync(0xffffffffu, qd, 1);
    qd += __shfl_xor_sync(0xffffffffu, qd, 2);
    mloc = fmaxf(mloc, qd);
  }
#pragma unroll
  for (int off = 4; off < 32; off <<= 1) {
    s4.x += __shfl_xor_sync(0xffffffffu, s4.x, off);
    s4.y += __shfl_xor_sync(0xffffffffu, s4.y, off);
    s4.z += __shfl_xor_sync(0xffffffffu, s4.z, off);
    s4.w += __shfl_xor_sync(0xffffffffu, s4.w, off);
    mloc = fmaxf(mloc, __shfl_xor_sync(0xffffffffu, mloc, off));
  }
  if (lane < 4) *reinterpret_cast<float4*>(&sm->wpart[w][lane * 4]) = s4;
  if (lane == 0) sm->wmax[w] = mloc;

  // ---- Load W slices in two layouts ----
#pragma unroll 1
  for (int idx2 = tid; idx2 < 4096; idx2 += THREADS) {  // [ml][d][c]
    int ml = idx2 >> 8, d = (idx2 >> 4) & 15, c = idx2 & 15;
    float val = Wg[d * 512 + (m0 + ml) * 16 + c];
    sm->Wdc[idx2] = val;
    sm->Wcd[ml * 256 + c * 16 + d] = val;
  }
  __syncthreads();

  if (tid < 16) {
    float s = 0.f;
#pragma unroll
    for (int ww = 0; ww < 12; ++ww) s += sm->wpart[ww][tid];
    sm->sumx[tid] = s;
  }
  if (tid == 16) {
    float mx = 0.f;
#pragma unroll
    for (int ww = 0; ww < 12; ++ww) mx = fmaxf(mx, sm->wmax[ww]);
    sm->mxnorm = sqrtf(mx);
  }

  // 12 main-loop warps: quad = w & 3 (4 caps each), chunk = w >> 2 (3 row chunks)
  const int quad  = w & 3;
  const int chunk = w >> 2;
  const int mlb   = 4 * quad;
  const int rstart = (chunk == 0) ? 0 : (chunk == 1 ? 704 : 1376);
  const int nsteps = (chunk == 0) ? 22 : 21;
  const float* xbase = &sm->u.xs[(rstart + lane) * XSTRIDE];

  for (int it = 0; it < 3; ++it) {
    if (it > 0) {
      // ---- fused logit(log2) + EX2 + weighted-sum pass, 4 caps per x read ----
      ull p[4][8], y[4][8], ib[4];
      float Z[4];
#pragma unroll
      for (int c = 0; c < 4; ++c) {
#pragma unroll
        for (int j = 0; j < 8; ++j) {
          p[c][j] = *reinterpret_cast<const ull*>(&sm->Pacc[mlb + c][2 * j]);
          y[c][j] = 0ull;
        }
        ib[c] = packlh(-sm->bnd[mlb + c], 0.f);
        Z[c] = 0.f;
      }
#pragma unroll 1
      for (int s = 0; s < nsteps; ++s) {
        ull xx[8];
        loadx(xx, xbase + s * (32 * XSTRIDE));
#pragma unroll
        for (int c = 0; c < 4; ++c) {
          ull a0 = fma2(xx[0], p[c][0], ib[c]);   // bound pre-folded
          ull a1 = mul2(xx[1], p[c][1]);
#pragma unroll
          for (int j = 1; j < 4; ++j) {
            a0 = fma2(xx[2 * j],     p[c][2 * j],     a0);
            a1 = fma2(xx[2 * j + 1], p[c][2 * j + 1], a1);
          }
          float e = ex2f(hadd2(add2(a0, a1)));
          Z[c] += e;
          ull e2 = pack2(e);
#pragma unroll
          for (int j = 0; j < 8; ++j) y[c][j] = fma2(e2, xx[j], y[c][j]);
        }
      }
      // 4-level warp reduction -> 2 partials (lanes 0,1)
#pragma unroll
      for (int off = 16; off >= 2; off >>= 1) {
#pragma unroll
        for (int c = 0; c < 4; ++c) {
          Z[c] += __shfl_xor_sync(0xffffffffu, Z[c], off);
#pragma unroll
          for (int j = 0; j < 8; ++j)
            y[c][j] = add2(y[c][j], __shfl_xor_sync(0xffffffffu, y[c][j], off));
        }
      }
      if (lane < 2) {
#pragma unroll
        for (int c = 0; c < 4; ++c) {
          sm->r.partZ[mlb + c][chunk][lane] = Z[c];
#pragma unroll
          for (int j = 0; j < 8; ++j)
            *reinterpret_cast<ull*>(&sm->r.party[mlb + c][chunk][lane][2 * j]) = y[c][j];
        }
      }
      __syncthreads();

      // ---- stage 1: fold 6 partials per (cap,d) and per cap ----
      if (tid < 256) {
        const int cap = tid >> 4, d = tid & 15;
        float acc = 0.f;
#pragma unroll
        for (int ch = 0; ch < 3; ++ch)
          acc += sm->r.party[cap][ch][0][d] + sm->r.party[cap][ch][1][d];
        sm->r.yfull[cap][d] = acc;
      } else if (tid < 272) {
        const int cap = tid - 256;
        float acc = 0.f;
#pragma unroll
        for (int ch = 0; ch < 3; ++ch)
          acc += sm->r.partZ[cap][ch][0] + sm->r.partZ[cap][ch][1];
        sm->r.Zfull[cap] = acc;
      }
    }
    __syncthreads();

    // ---- per-capsule epilogue: s = yW/Z, squash, Pacc += log2e * W v, bound ----
    if (w < 8) {
      const int ml  = w * 2 + (lane >> 4);
      const int idx = lane & 15;
      float Z = (it == 0) ? 2048.f : sm->r.Zfull[ml];
      float s = 0.f;
#pragma unroll
      for (int d = 0; d < 16; ++d) {
        float yv = (it == 0) ? sm->sumx[d] : sm->r.yfull[ml][d];
        s += yv * sm->Wdc[(ml * 16 + d) * 16 + idx];
      }
      s *= (1.f / Z);
      float nsq = s * s;
#pragma unroll
      for (int off = 1; off < 16; off <<= 1) nsq += __shfl_xor_sync(0xffffffffu, nsq, off);
      float norm = sqrtf(nsq);
      float fac  = nsq / ((1.f + nsq) * (norm + 1e-7f));
      float v    = s * fac;
      if (it == 2) {
        Y[(size_t)b * 512 + (m0 + ml) * 16 + idx] = v;
      } else {
        sm->vbuf[ml][idx] = v;
        __syncwarp();
        float pd = 0.f;
#pragma unroll
        for (int c = 0; c < 16; ++c)
          pd += sm->Wcd[(ml * 16 + c) * 16 + idx] * sm->vbuf[ml][c];
        float pn = sm->Pacc[ml][idx] + LOG2E * pd;
        sm->Pacc[ml][idx] = pn;
        float cn = pn * pn;
#pragma unroll
        for (int off = 1; off < 16; off <<= 1) cn += __shfl_xor_sync(0xffffffffu, cn, off);
        if (idx == 0) sm->bnd[ml] = sqrtf(cn) * sm->mxnorm;
      }
    }
    __syncthreads();
  }
}

extern "C" void kernel_launch(void* const* d_in, const int* in_sizes, int n_in,
                              void* d_out, int out_size) {
  (void)in_sizes; (void)n_in; (void)out_size;
  const float* X  = (const float*)d_in[0];   // inputs (64, 2048, 16)
  const float* Wg = (const float*)d_in[1];   // W (16, 32, 16)
  float* Y = (float*)d_out;                  // v (64, 32, 16)
  cudaFuncSetAttribute(caps_routing_kernel,
                       cudaFuncAttributeMaxDynamicSharedMemorySize, (int)sizeof(Smem));
  caps_routing_kernel<<<128, THREADS, sizeof(Smem)>>>(X, Wg, Y);
}

// round 8
// speedup vs baseline: 1.4841x; 1.2267x over previous
#include <cuda_runtime.h>

// CapsuleLayer dynamic routing, algebraically collapsed:
//   b[n,m] = x[n,:] @ Pacc[:,m]   (Pacc accumulates log2e * W@v across iterations)
//   s[m,:] = (1/Z) (e^T x) W[:,m,:],  v = squash(s),  Pacc[:,m] += log2e*W[:,m,:] v
// u_hat (268MB) never materialized. Softmax stabilized by Cauchy-Schwarz bound
// |l| <= max_n||x_n|| * ||Pacc_col||, in log2 domain so exp = single EX2.
// R8: C=2/512thr/16-warp shape; ptxas-driven pipelining (unroll 4, no manual
//     buffering) + per-warp step rotation to break cross-warp phase-lock of
//     LDS/FMA bursts.

#define NROW    2048
#define DIN     16
#define XSTRIDE 20
#define THREADS 512
#define LOG2E   1.4426950408889634f

typedef unsigned long long ull;

struct Smem {
  float xs[NROW * XSTRIDE];     // padded x rows (conflict-free stride 80B)
  float Wdc[16 * 16 * 16];      // [ml][d][c]
  float Wcd[16 * 16 * 16];      // [ml][c][d]
  float Pacc[16][16];           // [ml][d]  (scaled by log2e)
  float party[2][4][16][16];    // [chunk][lanegrp][ml][d]
  float partZ[2][4][16];        // [chunk][lanegrp][ml]
  float wpart[16][16];          // per-warp partial column sums of x
  float wmax[16];               // per-warp max row-norm^2
  float sumx[16];               // sum over n of x[n,d]
  float vbuf[16][16];           // [ml][c]
  float bnd[16];                // softmax shift bound per ml (log2 domain)
  float mxnorm;
  float pad[3];
};

__device__ __forceinline__ ull mul2(ull a, ull b) {
  ull d; asm("mul.rn.f32x2 %0, %1, %2;" : "=l"(d) : "l"(a), "l"(b)); return d;
}
__device__ __forceinline__ ull add2(ull a, ull b) {
  ull d; asm("add.rn.f32x2 %0, %1, %2;" : "=l"(d) : "l"(a), "l"(b)); return d;
}
__device__ __forceinline__ ull fma2(ull a, ull b, ull c) {
  ull d; asm("fma.rn.f32x2 %0, %1, %2, %3;" : "=l"(d) : "l"(a), "l"(b), "l"(c)); return d;
}
__device__ __forceinline__ ull pack2(float x) {
  ull d; asm("mov.b64 %0, {%1, %1};" : "=l"(d) : "f"(x)); return d;
}
__device__ __forceinline__ ull packlh(float lo, float hi) {
  ull d; asm("mov.b64 %0, {%1, %2};" : "=l"(d) : "f"(lo), "f"(hi)); return d;
}
__device__ __forceinline__ float hadd2(ull a) {
  float lo, hi; asm("mov.b64 {%0, %1}, %2;" : "=f"(lo), "=f"(hi) : "l"(a)); return lo + hi;
}
__device__ __forceinline__ float ex2f(float x) {
  float r; asm("ex2.approx.f32 %0, %1;" : "=f"(r) : "f"(x)); return r;
}

__global__ void __launch_bounds__(THREADS, 1)
caps_routing_kernel(const float* __restrict__ X, const float* __restrict__ Wg,
                    float* __restrict__ Y) {
  extern __shared__ char smraw[];
  Smem* sm = reinterpret_cast<Smem*>(smraw);
  const int tid  = threadIdx.x;
  const int lane = tid & 31;
  const int w    = tid >> 5;
  const int b    = blockIdx.x >> 1;
  const int m0   = (blockIdx.x & 1) * 16;

  if (tid < 256) ((float*)sm->Pacc)[tid] = 0.f;
  if (tid < 16)  sm->bnd[tid] = 0.f;

  // ---- Load x tile (128KB) into padded smem; fold in column sums + max row norm ----
  const float4* Xb = reinterpret_cast<const float4*>(X + (size_t)b * NROW * DIN);
  const int q = tid & 3;
  float4 s4 = make_float4(0.f, 0.f, 0.f, 0.f);
  float mloc = 0.f;
#pragma unroll
  for (int i = 0; i < 16; ++i) {
    int idx = tid + THREADS * i;
    int n = idx >> 2;
    float4 v = Xb[idx];
    *reinterpret_cast<float4*>(&sm->xs[n * XSTRIDE + q * 4]) = v;
    s4.x += v.x; s4.y += v.y; s4.z += v.z; s4.w += v.w;
    float qd = v.x * v.x + v.y * v.y + v.z * v.z + v.w * v.w;
    qd += __shfl_xor_sync(0xffffffffu, qd, 1);
    qd += __shfl_xor_sync(0xffffffffu, qd, 2);
    mloc = fmaxf(mloc, qd);
  }
#pragma unroll
  for (int off = 4; off < 32; off <<= 1) {
    s4.x += __shfl_xor_sync(0xffffffffu, s4.x, off);
    s4.y += __shfl_xor_sync(0xffffffffu, s4.y, off);
    s4.z += __shfl_xor_sync(0xffffffffu, s4.z, off);
    s4.w += __shfl_xor_sync(0xffffffffu, s4.w, off);
    mloc = fmaxf(mloc, __shfl_xor_sync(0xffffffffu, mloc, off));
  }
  if (lane < 4) *reinterpret_cast<float4*>(&sm->wpart[w][lane * 4]) = s4;
  if (lane == 0) sm->wmax[w] = mloc;

  // ---- Load W slices in two layouts ----
#pragma unroll
  for (int i = 0; i < 8; ++i) {
    int idx2 = tid + THREADS * i;         // [ml][d][c]
    int ml = idx2 >> 8, d = (idx2 >> 4) & 15, c = idx2 & 15;
    float val = Wg[d * 512 + (m0 + ml) * 16 + c];
    sm->Wdc[idx2] = val;
    sm->Wcd[ml * 256 + c * 16 + d] = val;
  }
  __syncthreads();

  if (tid < 16) {
    float s = 0.f;
#pragma unroll
    for (int ww = 0; ww < 16; ++ww) s += sm->wpart[ww][tid];
    sm->sumx[tid] = s;
  }
  if (tid == 16) {
    float mx = 0.f;
#pragma unroll
    for (int ww = 0; ww < 16; ++ww) mx = fmaxf(mx, sm->wmax[ww]);
    sm->mxnorm = sqrtf(mx);
  }

  const int g     = w & 7;        // capsule pair group
  const int chunk = w >> 3;       // row chunk (0: 0-1023, 1: 1024-2047)
  const int mlb   = 2 * g;
  const int rot   = (w & 3) * 8;  // per-warp step rotation (breaks phase-lock)
  const float* xbase = &sm->xs[(chunk * 1024 + lane) * XSTRIDE];
  const int XSTEP = 32 * XSTRIDE;

  for (int it = 0; it < 3; ++it) {
    if (it > 0) {
      // ---- fused logit(log2) + EX2 + weighted-sum pass ----
      ull p[2][8], y[2][8], ib[2];
      float Z[2];
#pragma unroll
      for (int c = 0; c < 2; ++c) {
#pragma unroll
        for (int j = 0; j < 8; ++j) {
          p[c][j] = *reinterpret_cast<const ull*>(&sm->Pacc[mlb + c][2 * j]);
          y[c][j] = 0ull;
        }
        ib[c] = packlh(-sm->bnd[mlb + c], 0.f);
        Z[c] = 0.f;
      }
#pragma unroll 4
      for (int s = 0; s < 32; ++s) {
        const int se = (s + rot) & 31;
        const ulonglong2* xp =
            reinterpret_cast<const ulonglong2*>(xbase + se * XSTEP);
        ulonglong2 q0 = xp[0], q1 = xp[1], q2 = xp[2], q3 = xp[3];
        ull xx[8];
        xx[0] = q0.x; xx[1] = q0.y; xx[2] = q1.x; xx[3] = q1.y;
        xx[4] = q2.x; xx[5] = q2.y; xx[6] = q3.x; xx[7] = q3.y;
#pragma unroll
        for (int c = 0; c < 2; ++c) {
          ull a0 = fma2(xx[0], p[c][0], ib[c]);   // bound pre-folded
          ull a1 = mul2(xx[1], p[c][1]);
#pragma unroll
          for (int j = 1; j < 4; ++j) {
            a0 = fma2(xx[2 * j],     p[c][2 * j],     a0);
            a1 = fma2(xx[2 * j + 1], p[c][2 * j + 1], a1);
          }
          float e = ex2f(hadd2(add2(a0, a1)));
          Z[c] += e;
          ull e2 = pack2(e);
#pragma unroll
          for (int j = 0; j < 8; ++j) y[c][j] = fma2(e2, xx[j], y[c][j]);
        }
      }

      // 3-level warp reduction -> 4 partials (lanes 0..3)
#pragma unroll
      for (int off = 16; off >= 4; off >>= 1) {
#pragma unroll
        for (int c = 0; c < 2; ++c) {
          Z[c] += __shfl_xor_sync(0xffffffffu, Z[c], off);
#pragma unroll
          for (int j = 0; j < 8; ++j)
            y[c][j] = add2(y[c][j], __shfl_xor_sync(0xffffffffu, y[c][j], off));
        }
      }
      if (lane < 4) {
#pragma unroll
        for (int c = 0; c < 2; ++c) {
          sm->partZ[chunk][lane][mlb + c] = Z[c];
#pragma unroll
          for (int j = 0; j < 8; ++j)
            *reinterpret_cast<ull*>(&sm->party[chunk][lane][mlb + c][2 * j]) = y[c][j];
        }
      }
    }
    __syncthreads();

    // ---- per-capsule epilogue: s = yW/Z, squash, Pacc += log2e * W v, bound ----
    if (w < 8) {
      const int ml  = w * 2 + (lane >> 4);
      const int idx = lane & 15;
      float Z, yv;
      if (it == 0) {
        Z = 2048.f;
      } else {
        Z = 0.f;
#pragma unroll
        for (int cg = 0; cg < 4; ++cg) Z += sm->partZ[0][cg][ml] + sm->partZ[1][cg][ml];
      }
      float s = 0.f;
#pragma unroll
      for (int d = 0; d < 16; ++d) {
        if (it == 0) {
          yv = sm->sumx[d];
        } else {
          yv = 0.f;
#pragma unroll
          for (int cg = 0; cg < 4; ++cg)
            yv += sm->party[0][cg][ml][d] + sm->party[1][cg][ml][d];
        }
        s += yv * sm->Wdc[(ml * 16 + d) * 16 + idx];
      }
      s *= (1.f / Z);
      float nsq = s * s;
#pragma unroll
      for (int off = 1; off < 16; off <<= 1) nsq += __shfl_xor_sync(0xffffffffu, nsq, off);
      float norm = sqrtf(nsq);
      float fac  = nsq / ((1.f + nsq) * (norm + 1e-7f));
      float v    = s * fac;
      if (it == 2) {
        Y[(size_t)b * 512 + (m0 + ml) * 16 + idx] = v;
      } else {
        sm->vbuf[ml][idx] = v;
        __syncwarp();
        float pd = 0.f;
#pragma unroll
        for (int c = 0; c < 16; ++c)
          pd += sm->Wcd[(ml * 16 + c) * 16 + idx] * sm->vbuf[ml][c];
        float pn = sm->Pacc[ml][idx] + LOG2E * pd;
        sm->Pacc[ml][idx] = pn;
        float cn = pn * pn;
#pragma unroll
        for (int off = 1; off < 16; off <<= 1) cn += __shfl_xor_sync(0xffffffffu, cn, off);
        if (idx == 0) sm->bnd[ml] = sqrtf(cn) * sm->mxnorm;
      }
    }
    __syncthreads();
  }
}

extern "C" void kernel_launch(void* const* d_in, const int* in_sizes, int n_in,
                              void* d_out, int out_size) {
  (void)in_sizes; (void)n_in; (void)out_size;
  const float* X  = (const float*)d_in[0];   // inputs (64, 2048, 16)
  const float* Wg = (const float*)d_in[1];   // W (16, 32, 16)
  float* Y = (float*)d_out;                  // v (64, 32, 16)
  cudaFuncSetAttribute(caps_routing_kernel,
                       cudaFuncAttributeMaxDynamicSharedMemorySize, (int)sizeof(Smem));
  caps_routing_kernel<<<128, THREADS, sizeof(Smem)>>>(X, Wg, Y);
}